// round 3
// baseline (speedup 1.0000x reference)
#include <cuda_runtime.h>
#include <cuda_bf16.h>
#include <math.h>

// Problem constants
#define QS 256
#define LS 2048
#define NB 64
#define SS 26
#define NPOST (NB * LS * QS)     // 33,554,432
#define EM_ROWS 64

// A split per thread (column tid):
//   rows   0..159 : fp32 in registers (80 packed u64 = 160 regs)
//   rows 160..223 : bf16 in registers (32 u32 regs)
//   rows 224..255 : bf16 in shared    (16 u32 per thread, 4x LDS.128)
#define ROWPITCH_U32 20          // 16 payload words + 4 pad
#define RENORM_MASK 15

// ---------------------------------------------------------------------------
// Device scratch
// ---------------------------------------------------------------------------
__device__ float g_expA[QS * QS];     // exp(log_A)  [j][i]
__device__ float g_expAT[QS * QS];    // transpose
__device__ float g_expB[QS * 32];     // exp(log_B) padded
__device__ float g_pi[QS];
__device__ float g_emit[NPOST];       // [b][l][q]
__device__ float g_alpha[NPOST];      // unnormalized-within-block alpha~
__device__ float g_beta[NPOST];       // unnormalized-within-block beta~
__device__ float g_Ca[NB * LS];       // piecewise-constant forward log-scale
__device__ float g_Cb[NB * LS];       // piecewise-constant backward log-scale
__device__ float g_loglik[NB];

// ---------------------------------------------------------------------------
// f32x2 helpers (sm_103a packed fp32 math)
// ---------------------------------------------------------------------------
__device__ __forceinline__ unsigned long long pk(float x, float y) {
    unsigned long long r;
    asm("mov.b64 %0, {%1,%2};" : "=l"(r) : "f"(x), "f"(y));
    return r;
}
__device__ __forceinline__ void ffma2(unsigned long long& c,
                                      unsigned long long a,
                                      unsigned long long b) {
    asm("fma.rn.f32x2 %0, %1, %2, %0;" : "+l"(c) : "l"(a), "l"(b));
}
__device__ __forceinline__ float2 unpk(unsigned long long u) {
    float lo, hi;
    asm("mov.b64 {%0,%1}, %2;" : "=f"(lo), "=f"(hi) : "l"(u));
    return make_float2(lo, hi);
}
// bf16x2 word -> packed f32x2 (exact widening)
__device__ __forceinline__ unsigned long long bf2f(unsigned int w) {
    unsigned int lo = w << 16;
    unsigned int hi = w & 0xffff0000u;
    unsigned long long r;
    asm("mov.b64 %0, {%1,%2};" : "=l"(r) : "r"(lo), "r"(hi));
    return r;
}
__device__ __forceinline__ unsigned int pack_bf16(float a, float b) {
    __nv_bfloat16 b0 = __float2bfloat16(a);
    __nv_bfloat16 b1 = __float2bfloat16(b);
    return (unsigned int)__bfloat16_as_ushort(b0) |
           ((unsigned int)__bfloat16_as_ushort(b1) << 16);
}

// ---------------------------------------------------------------------------
// Kernel 0: exp() of parameters
// ---------------------------------------------------------------------------
__global__ void precompute_kernel(const float* __restrict__ log_A,
                                  const float* __restrict__ log_pi,
                                  const float* __restrict__ log_B) {
    int idx = blockIdx.x * 256 + threadIdx.x;
    if (blockIdx.x < 256) {
        float v = expf(log_A[idx]);
        g_expA[idx] = v;
        int j = idx >> 8, i = idx & 255;
        g_expAT[i * QS + j] = v;
    } else if (blockIdx.x < 282) {
        int k = idx - 65536;
        if (k < QS * SS) {
            int q = k / SS, s = k - q * SS;
            g_expB[q * 32 + s] = expf(log_B[k]);
        }
    } else {
        if (threadIdx.x < QS) g_pi[threadIdx.x] = expf(log_pi[threadIdx.x]);
    }
}

// ---------------------------------------------------------------------------
// Kernel 1: emission GEMM  emit[b,l,q] = sum_s inputs[b,l,s] * expB[q,s]
// ---------------------------------------------------------------------------
__global__ void __launch_bounds__(256) emission_kernel(const float* __restrict__ inputs) {
    __shared__ float in_sh[EM_ROWS][SS];
    int tid = threadIdx.x;
    int row0 = blockIdx.x * EM_ROWS;

    for (int i = tid; i < EM_ROWS * SS; i += 256)
        in_sh[i / SS][i % SS] = inputs[row0 * SS + i];
    float eb[SS];
#pragma unroll
    for (int s = 0; s < SS; s++) eb[s] = g_expB[tid * 32 + s];
    __syncthreads();

#pragma unroll 4
    for (int r = 0; r < EM_ROWS; r++) {
        float acc = 0.0f;
#pragma unroll
        for (int s = 0; s < SS; s++) acc = fmaf(in_sh[r][s], eb[s], acc);
        g_emit[(size_t)(row0 + r) * QS + tid] = acc;
    }
}

// ---------------------------------------------------------------------------
// Block reduction (only on renorm steps)
// ---------------------------------------------------------------------------
__device__ __forceinline__ float block_sum(float v, float* red, int tid) {
#pragma unroll
    for (int o = 16; o > 0; o >>= 1) v += __shfl_xor_sync(0xffffffffu, v, o);
    if ((tid & 31) == 0) red[tid >> 5] = v;
    __syncthreads();
    float s = 0.0f;
#pragma unroll
    for (int w = 0; w < 8; w++) s += red[w];
    return s;
}

// mv[i] = A(:,tid) . p  with the 3-way A split, 4 packed accumulators
__device__ __forceinline__ float matvec256(const unsigned long long* __restrict__ Areg,
                                           const unsigned int* __restrict__ Abf,
                                           const uint4* __restrict__ arow,
                                           const float4* __restrict__ pc4) {
    unsigned long long a0 = 0ull, a1 = 0ull, a2 = 0ull, a3 = 0ull;
    // rows 0..159 (fp32 regs)
#pragma unroll
    for (int k = 0; k < 20; k++) {
        float4 p0 = pc4[2 * k];
        float4 p1 = pc4[2 * k + 1];
        ffma2(a0, Areg[4 * k + 0], pk(p0.x, p0.y));
        ffma2(a1, Areg[4 * k + 1], pk(p0.z, p0.w));
        ffma2(a2, Areg[4 * k + 2], pk(p1.x, p1.y));
        ffma2(a3, Areg[4 * k + 3], pk(p1.z, p1.w));
    }
    // rows 160..223 (bf16 regs)
#pragma unroll
    for (int k = 0; k < 8; k++) {
        float4 p0 = pc4[40 + 2 * k];
        float4 p1 = pc4[40 + 2 * k + 1];
        ffma2(a0, bf2f(Abf[4 * k + 0]), pk(p0.x, p0.y));
        ffma2(a1, bf2f(Abf[4 * k + 1]), pk(p0.z, p0.w));
        ffma2(a2, bf2f(Abf[4 * k + 2]), pk(p1.x, p1.y));
        ffma2(a3, bf2f(Abf[4 * k + 3]), pk(p1.z, p1.w));
    }
    // rows 224..255 (bf16 shared, 4x LDS.128)
#pragma unroll
    for (int k = 0; k < 4; k++) {
        uint4 w = arow[k];
        float4 p0 = pc4[56 + 2 * k];
        float4 p1 = pc4[56 + 2 * k + 1];
        ffma2(a0, bf2f(w.x), pk(p0.x, p0.y));
        ffma2(a1, bf2f(w.y), pk(p0.z, p0.w));
        ffma2(a2, bf2f(w.z), pk(p1.x, p1.y));
        ffma2(a3, bf2f(w.w), pk(p1.z, p1.w));
    }
    float2 f0 = unpk(a0), f1 = unpk(a1), f2 = unpk(a2), f3 = unpk(a3);
    return ((f0.x + f0.y) + (f1.x + f1.y)) + ((f2.x + f2.y) + (f3.x + f3.y));
}

// ---------------------------------------------------------------------------
// Kernel 2: scaled forward/backward with deferred renormalization.
// Block 0..63 forward chain b; block 64..127 backward chain b-64.
// ---------------------------------------------------------------------------
extern __shared__ float sh[];

#define SH_A_U32   ((unsigned int*)sh)
#define SH_P(buf)  (sh + QS * ROWPITCH_U32 + (buf) * QS)
#define SH_RED     (sh + QS * ROWPITCH_U32 + 2 * QS)

__global__ void __launch_bounds__(256, 1) fb_kernel() {
    int tid = threadIdx.x;
    int bx = blockIdx.x;
    bool fwd = (bx < NB);
    int b = fwd ? bx : bx - NB;
    const float* Ag = fwd ? g_expA : g_expAT;

    // rows 0..159 -> fp32 register pairs
    unsigned long long Areg[80];
#pragma unroll
    for (int k = 0; k < 80; k++)
        Areg[k] = pk(Ag[(2 * k) * QS + tid], Ag[(2 * k + 1) * QS + tid]);

    // rows 160..223 -> bf16 register pairs
    unsigned int Abf[32];
#pragma unroll
    for (int m = 0; m < 32; m++)
        Abf[m] = pack_bf16(Ag[(160 + 2 * m) * QS + tid], Ag[(161 + 2 * m) * QS + tid]);

    // rows 224..255 -> bf16 pairs in this thread's private shared row
    unsigned int* myrow = SH_A_U32 + tid * ROWPITCH_U32;
    for (int m = 0; m < 16; m++)
        myrow[m] = pack_bf16(Ag[(224 + 2 * m) * QS + tid], Ag[(225 + 2 * m) * QS + tid]);
    const uint4* arow = (const uint4*)myrow;

    const float* em_b = g_emit + (size_t)b * LS * QS;
    float* st_b = (fwd ? g_alpha : g_beta) + (size_t)b * LS * QS;
    float* C_b  = (fwd ? g_Ca : g_Cb) + b * LS;
    float* red  = SH_RED;

    double C = 0.0;
    int cur = 0;

    if (fwd) {
        float v = g_pi[tid] * em_b[tid];
        st_b[tid] = v;
        if (tid == 0) C_b[0] = 0.0f;
        SH_P(0)[tid] = v;
        __syncthreads();

        for (int t = 1; t < LS; t++) {
            float e  = em_b[(size_t)t * QS + tid];
            float mv = matvec256(Areg, Abf, arow, (const float4*)SH_P(cur));
            float v2 = mv * e;
            float Ct = (float)C;
            float pn = v2;
            if ((t & RENORM_MASK) == RENORM_MASK) {
                float s = block_sum(v2, red, tid);
                pn = v2 * (1.0f / s);
                if (t == LS - 1 && tid == 0)
                    g_loglik[b] = (float)(C + (double)logf(s));
                C += (double)logf(s);
            }
            SH_P(cur ^ 1)[tid] = pn;
            __syncthreads();
            // stores overlap next step's matvec
            st_b[(size_t)t * QS + tid] = v2;
            if (tid == 0) C_b[t] = Ct;
            cur ^= 1;
        }
    } else {
        st_b[(size_t)(LS - 1) * QS + tid] = 1.0f;
        if (tid == 0) C_b[LS - 1] = 0.0f;
        SH_P(0)[tid] = em_b[(size_t)(LS - 1) * QS + tid];  // w = e_{t+1} * beta~_{t+1}
        __syncthreads();

        for (int t = LS - 2; t >= 0; t--) {
            float e  = em_b[(size_t)t * QS + tid];
            float v  = matvec256(Areg, Abf, arow, (const float4*)SH_P(cur));
            float Ct = (float)C;
            float q = v;
            if ((t & RENORM_MASK) == 0) {
                float s = block_sum(v, red, tid);
                q = v * (1.0f / s);
                C += (double)logf(s);
            }
            SH_P(cur ^ 1)[tid] = e * q;
            __syncthreads();
            st_b[(size_t)t * QS + tid] = v;
            if (tid == 0) C_b[t] = Ct;
            cur ^= 1;
        }
    }
}

// ---------------------------------------------------------------------------
// Kernel 3: posterior + loglik (float4, single log per element)
// ---------------------------------------------------------------------------
__global__ void __launch_bounds__(256) posterior_kernel(float* __restrict__ out, int out_size) {
    int i4 = blockIdx.x * 256 + threadIdx.x;   // 0 .. NPOST/4-1
    int idx = i4 << 2;
    int bt = idx >> 8;
    int b  = bt >> 11;
    float4 a  = *(const float4*)(g_alpha + idx);
    float4 be = *(const float4*)(g_beta + idx);
    float c = g_Ca[bt] + g_Cb[bt] - g_loglik[b];
    float4 o;
    o.x = logf(a.x * be.x) + c;
    o.y = logf(a.y * be.y) + c;
    o.z = logf(a.z * be.z) + c;
    o.w = logf(a.w * be.w) + c;
    *(float4*)(out + idx) = o;
    if (i4 < NB && out_size >= NPOST + NB)
        out[NPOST + i4] = g_loglik[i4];
}

// ---------------------------------------------------------------------------
// Launch
// ---------------------------------------------------------------------------
extern "C" void kernel_launch(void* const* d_in, const int* in_sizes, int n_in,
                              void* d_out, int out_size) {
    const float* inputs = (const float*)d_in[0];   // (1,64,2048,26)
    const float* log_A  = (const float*)d_in[1];   // (1,256,256)
    const float* log_pi = (const float*)d_in[2];   // (1,256)
    const float* log_B  = (const float*)d_in[3];   // (1,256,26)
    float* out = (float*)d_out;

    precompute_kernel<<<283, 256>>>(log_A, log_pi, log_B);
    emission_kernel<<<(NB * LS) / EM_ROWS, 256>>>(inputs);

    int smem = (QS * ROWPITCH_U32 + 2 * QS + 16) * (int)sizeof(float);
    cudaFuncSetAttribute(fb_kernel, cudaFuncAttributeMaxDynamicSharedMemorySize, smem);
    fb_kernel<<<2 * NB, 256, smem>>>();

    posterior_kernel<<<NPOST / 1024, 256>>>(out, out_size);
}

// round 4
// speedup vs baseline: 1.4427x; 1.4427x over previous
#include <cuda_runtime.h>
#include <cuda_bf16.h>
#include <math.h>

// Problem constants
#define QS 256
#define LS 2048
#define NB 64
#define SS 26
#define NPOST (NB * LS * QS)     // 33,554,432
#define EM_ROWS 64

// A split per thread (column tid):  rows 0..159 fp32 regs, rows 160..255 bf16 shared
#define REGROWS 160
#define SHROWS  96
#define ROWPITCH_U32 52          // 48 payload words + 4 pad -> conflict-free LDS.128
#define RENORM_MASK 15

// ---------------------------------------------------------------------------
// Device scratch
// ---------------------------------------------------------------------------
__device__ float g_expA[QS * QS];     // exp(log_A)  [j][i]
__device__ float g_expAT[QS * QS];    // transpose
__device__ float g_expB[QS * 32];     // exp(log_B) padded
__device__ float g_pi[QS];
__device__ float g_emit[NPOST];       // [b][l][q]
__device__ float g_alpha[NPOST];      // unnormalized-within-block alpha~
__device__ float g_beta[NPOST];       // unnormalized-within-block beta~
__device__ float g_Ca[NB * LS];       // piecewise-constant forward log-scale
__device__ float g_Cb[NB * LS];       // piecewise-constant backward log-scale
__device__ float g_loglik[NB];

// ---------------------------------------------------------------------------
// f32x2 helpers (sm_103a packed fp32 math)
// ---------------------------------------------------------------------------
__device__ __forceinline__ unsigned long long pk(float x, float y) {
    unsigned long long r;
    asm("mov.b64 %0, {%1,%2};" : "=l"(r) : "f"(x), "f"(y));
    return r;
}
__device__ __forceinline__ void ffma2(unsigned long long& c,
                                      unsigned long long a,
                                      unsigned long long b) {
    asm("fma.rn.f32x2 %0, %1, %2, %0;" : "+l"(c) : "l"(a), "l"(b));
}
__device__ __forceinline__ float2 unpk(unsigned long long u) {
    float lo, hi;
    asm("mov.b64 {%0,%1}, %2;" : "=f"(lo), "=f"(hi) : "l"(u));
    return make_float2(lo, hi);
}
// bf16x2 word -> packed f32x2 (exact widening)
__device__ __forceinline__ unsigned long long bf2f(unsigned int w) {
    unsigned int lo = w << 16;
    unsigned int hi = w & 0xffff0000u;
    unsigned long long r;
    asm("mov.b64 %0, {%1,%2};" : "=l"(r) : "r"(lo), "r"(hi));
    return r;
}
__device__ __forceinline__ unsigned int pack_bf16(float a, float b) {
    __nv_bfloat16 b0 = __float2bfloat16(a);
    __nv_bfloat16 b1 = __float2bfloat16(b);
    return (unsigned int)__bfloat16_as_ushort(b0) |
           ((unsigned int)__bfloat16_as_ushort(b1) << 16);
}

// ---------------------------------------------------------------------------
// Kernel 0: exp() of parameters
// ---------------------------------------------------------------------------
__global__ void precompute_kernel(const float* __restrict__ log_A,
                                  const float* __restrict__ log_pi,
                                  const float* __restrict__ log_B) {
    int idx = blockIdx.x * 256 + threadIdx.x;
    if (blockIdx.x < 256) {
        float v = expf(log_A[idx]);
        g_expA[idx] = v;
        int j = idx >> 8, i = idx & 255;
        g_expAT[i * QS + j] = v;
    } else if (blockIdx.x < 282) {
        int k = idx - 65536;
        if (k < QS * SS) {
            int q = k / SS, s = k - q * SS;
            g_expB[q * 32 + s] = expf(log_B[k]);
        }
    } else {
        if (threadIdx.x < QS) g_pi[threadIdx.x] = expf(log_pi[threadIdx.x]);
    }
}

// ---------------------------------------------------------------------------
// Kernel 1: emission GEMM  emit[b,l,q] = sum_s inputs[b,l,s] * expB[q,s]
// ---------------------------------------------------------------------------
__global__ void __launch_bounds__(256) emission_kernel(const float* __restrict__ inputs) {
    __shared__ float in_sh[EM_ROWS][SS];
    int tid = threadIdx.x;
    int row0 = blockIdx.x * EM_ROWS;

    for (int i = tid; i < EM_ROWS * SS; i += 256)
        in_sh[i / SS][i % SS] = inputs[row0 * SS + i];
    float eb[SS];
#pragma unroll
    for (int s = 0; s < SS; s++) eb[s] = g_expB[tid * 32 + s];
    __syncthreads();

#pragma unroll 4
    for (int r = 0; r < EM_ROWS; r++) {
        float acc = 0.0f;
#pragma unroll
        for (int s = 0; s < SS; s++) acc = fmaf(in_sh[r][s], eb[s], acc);
        g_emit[(size_t)(row0 + r) * QS + tid] = acc;
    }
}

// ---------------------------------------------------------------------------
// Block reduction (only on renorm steps)
// ---------------------------------------------------------------------------
__device__ __forceinline__ float block_sum(float v, float* red, int tid) {
#pragma unroll
    for (int o = 16; o > 0; o >>= 1) v += __shfl_xor_sync(0xffffffffu, v, o);
    if ((tid & 31) == 0) red[tid >> 5] = v;
    __syncthreads();
    float s = 0.0f;
#pragma unroll
    for (int w = 0; w < 8; w++) s += red[w];
    return s;
}

// mv[i] = sum_{j<160} p[j]*Areg + sum_{j in 160..255} p[j]*Ash(bf16)
// 4 independent packed accumulators; p read directly as f32x2 pairs (LDS.128)
__device__ __forceinline__ float matvec256(const unsigned long long* __restrict__ Areg,
                                           const uint4* __restrict__ arow,
                                           const ulonglong2* __restrict__ pc2) {
    unsigned long long a0 = 0ull, a1 = 0ull, a2 = 0ull, a3 = 0ull;
    // rows 0..159 (fp32 regs): 20 iters x 4 ffma2
#pragma unroll
    for (int k = 0; k < 20; k++) {
        ulonglong2 p0 = pc2[2 * k];
        ulonglong2 p1 = pc2[2 * k + 1];
        ffma2(a0, Areg[4 * k + 0], p0.x);
        ffma2(a1, Areg[4 * k + 1], p0.y);
        ffma2(a2, Areg[4 * k + 2], p1.x);
        ffma2(a3, Areg[4 * k + 3], p1.y);
    }
    // rows 160..255 (bf16 shared): 12 x LDS.128 A + 12 x LDS.128 p
#pragma unroll
    for (int k = 0; k < 12; k++) {
        uint4 w = arow[k];
        ulonglong2 p0 = pc2[40 + 2 * k];
        ulonglong2 p1 = pc2[40 + 2 * k + 1];
        ffma2(a0, bf2f(w.x), p0.x);
        ffma2(a1, bf2f(w.y), p0.y);
        ffma2(a2, bf2f(w.z), p1.x);
        ffma2(a3, bf2f(w.w), p1.y);
    }
    float2 f0 = unpk(a0), f1 = unpk(a1), f2 = unpk(a2), f3 = unpk(a3);
    return ((f0.x + f0.y) + (f1.x + f1.y)) + ((f2.x + f2.y) + (f3.x + f3.y));
}

// ---------------------------------------------------------------------------
// Kernel 2: scaled forward/backward with deferred renormalization.
// Block 0..63 forward chain b; block 64..127 backward chain b-64.
// ---------------------------------------------------------------------------
extern __shared__ float sh[];

#define SH_A_U32   ((unsigned int*)sh)
#define SH_P(buf)  (sh + QS * ROWPITCH_U32 + (buf) * QS)
#define SH_RED     (sh + QS * ROWPITCH_U32 + 2 * QS)

__global__ void __launch_bounds__(256, 1) fb_kernel() {
    int tid = threadIdx.x;
    int bx = blockIdx.x;
    bool fwd = (bx < NB);
    int b = fwd ? bx : bx - NB;
    const float* Ag = fwd ? g_expA : g_expAT;

    // rows 0..159 -> fp32 register pairs (exact)
    unsigned long long Areg[REGROWS / 2];
#pragma unroll
    for (int k = 0; k < REGROWS / 2; k++)
        Areg[k] = pk(Ag[(2 * k) * QS + tid], Ag[(2 * k + 1) * QS + tid]);

    // rows 160..255 -> bf16 pairs in this thread's private shared row
    unsigned int* myrow = SH_A_U32 + tid * ROWPITCH_U32;
    for (int m = 0; m < SHROWS / 2; m++)
        myrow[m] = pack_bf16(Ag[(REGROWS + 2 * m) * QS + tid],
                             Ag[(REGROWS + 2 * m + 1) * QS + tid]);
    const uint4* arow = (const uint4*)myrow;

    const float* em_b = g_emit + (size_t)b * LS * QS;
    float* st_b = (fwd ? g_alpha : g_beta) + (size_t)b * LS * QS;
    float* C_b  = (fwd ? g_Ca : g_Cb) + b * LS;
    float* red  = SH_RED;

    double C = 0.0;
    int cur = 0;

    if (fwd) {
        float v = g_pi[tid] * em_b[tid];
        st_b[tid] = v;
        if (tid == 0) C_b[0] = 0.0f;
        SH_P(0)[tid] = v;
        __syncthreads();

        for (int t = 1; t < LS; t++) {
            float e  = em_b[(size_t)t * QS + tid];
            float mv = matvec256(Areg, arow, (const ulonglong2*)SH_P(cur));
            float v2 = mv * e;
            float Ct = (float)C;
            float pn = v2;
            if ((t & RENORM_MASK) == RENORM_MASK) {
                float s = block_sum(v2, red, tid);
                pn = v2 * (1.0f / s);
                if (t == LS - 1 && tid == 0)
                    g_loglik[b] = (float)(C + (double)logf(s));
                C += (double)logf(s);
            }
            SH_P(cur ^ 1)[tid] = pn;
            __syncthreads();
            // stores overlap next step's matvec
            st_b[(size_t)t * QS + tid] = v2;
            if (tid == 0) C_b[t] = Ct;
            cur ^= 1;
        }
    } else {
        st_b[(size_t)(LS - 1) * QS + tid] = 1.0f;
        if (tid == 0) C_b[LS - 1] = 0.0f;
        SH_P(0)[tid] = em_b[(size_t)(LS - 1) * QS + tid];  // w = e_{t+1} * beta~_{t+1}
        __syncthreads();

        for (int t = LS - 2; t >= 0; t--) {
            float e  = em_b[(size_t)t * QS + tid];
            float v  = matvec256(Areg, arow, (const ulonglong2*)SH_P(cur));
            float Ct = (float)C;
            float q = v;
            if ((t & RENORM_MASK) == 0) {
                float s = block_sum(v, red, tid);
                q = v * (1.0f / s);
                C += (double)logf(s);
            }
            SH_P(cur ^ 1)[tid] = e * q;
            __syncthreads();
            st_b[(size_t)t * QS + tid] = v;
            if (tid == 0) C_b[t] = Ct;
            cur ^= 1;
        }
    }
}

// ---------------------------------------------------------------------------
// Kernel 3: posterior + loglik (float4, single log per element)
// ---------------------------------------------------------------------------
__global__ void __launch_bounds__(256) posterior_kernel(float* __restrict__ out, int out_size) {
    int i4 = blockIdx.x * 256 + threadIdx.x;   // 0 .. NPOST/4-1
    int idx = i4 << 2;
    int bt = idx >> 8;
    int b  = bt >> 11;
    float4 a  = *(const float4*)(g_alpha + idx);
    float4 be = *(const float4*)(g_beta + idx);
    float c = g_Ca[bt] + g_Cb[bt] - g_loglik[b];
    float4 o;
    o.x = logf(a.x * be.x) + c;
    o.y = logf(a.y * be.y) + c;
    o.z = logf(a.z * be.z) + c;
    o.w = logf(a.w * be.w) + c;
    *(float4*)(out + idx) = o;
    if (i4 < NB && out_size >= NPOST + NB)
        out[NPOST + i4] = g_loglik[i4];
}

// ---------------------------------------------------------------------------
// Launch
// ---------------------------------------------------------------------------
extern "C" void kernel_launch(void* const* d_in, const int* in_sizes, int n_in,
                              void* d_out, int out_size) {
    const float* inputs = (const float*)d_in[0];   // (1,64,2048,26)
    const float* log_A  = (const float*)d_in[1];   // (1,256,256)
    const float* log_pi = (const float*)d_in[2];   // (1,256)
    const float* log_B  = (const float*)d_in[3];   // (1,256,26)
    float* out = (float*)d_out;

    precompute_kernel<<<283, 256>>>(log_A, log_pi, log_B);
    emission_kernel<<<(NB * LS) / EM_ROWS, 256>>>(inputs);

    int smem = (QS * ROWPITCH_U32 + 2 * QS + 16) * (int)sizeof(float);
    cudaFuncSetAttribute(fb_kernel, cudaFuncAttributeMaxDynamicSharedMemorySize, smem);
    fb_kernel<<<2 * NB, 256, smem>>>();

    posterior_kernel<<<NPOST / 1024, 256>>>(out, out_size);
}